// round 5
// baseline (speedup 1.0000x reference)
#include <cuda_runtime.h>
#include <cstdint>
#include <cmath>

#define RDIM 2000
#define TSTEPS 20000
#define NCTA 125
#define COLS 16          // columns per CTA (125*16 = 2000)
#define NTHR 256         // 8 warps; warp w covers i in [w*256,(w+1)*256)
#define RPAD 2048
#define SPIN_CAP (1u << 18)

// Published state: (value, step-tag) pairs, double-buffered by step parity.
// buffer[t&1] holds h_t with tag == t. Init (tag 0) == h_0 == 0.
__device__ float2 g_hbuf[2][RPAD];
// Plain state buffers for the stepped fallback path.
__device__ float g_hs[2][RPAD];
// Watchdog: any spin exceeding SPIN_CAP sets this; all spins then bail out.
__device__ int g_abort;

__global__ void esn_init_kernel() {
    int idx = blockIdx.x * blockDim.x + threadIdx.x;   // 16*256 = 4096
    if (idx < 2 * RPAD) {
        ((float2*)g_hbuf)[idx] = make_float2(0.f, 0.f);
        ((float*)g_hs)[idx] = 0.f;
    }
    if (idx == 0) g_abort = 0;
}

__device__ __forceinline__ unsigned long long addx2(unsigned long long a,
                                                    unsigned long long b) {
    unsigned long long r;
    asm("add.rn.f32x2 %0,%1,%2;" : "=l"(r) : "l"(a), "l"(b));
    return r;
}

// ============================ FUSED (fast) PATH =============================
__global__ void __launch_bounds__(NTHR, 1) esn_kernel(
    const float* __restrict__ x,     // [T,1]
    const float* __restrict__ Win,   // [2,R]
    const float* __restrict__ W,     // [R,R] row-major
    const float* __restrict__ gain,  // [R]
    const float* __restrict__ bias,  // [R]
    float* __restrict__ out)         // [T,R]
{
    __shared__ __align__(16) float h_s[2][RPAD];
    __shared__ __align__(16) float part[COLS][8];   // per-warp column partials

    const int tid  = threadIdx.x;
    const int lane = tid & 31;
    const int w    = tid >> 5;
    const int cta  = blockIdx.x;
    const int j0   = cta * COLS;          // CTA's 16 columns
    const int ibase = w * 256 + lane * 8; // this thread's 8 consecutive i's

    // W slice: wreg[il*8+c] packs (W[i][j0+2c], W[i][j0+2c+1])
    unsigned long long wreg[64];
#pragma unroll
    for (int il = 0; il < 8; il++) {
        int i = ibase + il;
#pragma unroll
        for (int c = 0; c < 8; c++) {
            float a = (i < RDIM) ? W[(size_t)i * RDIM + j0 + 2 * c]     : 0.f;
            float b = (i < RDIM) ? W[(size_t)i * RDIM + j0 + 2 * c + 1] : 0.f;
            asm("mov.b64 %0,{%1,%2};" : "=l"(wreg[il * 8 + c])
                : "r"(__float_as_uint(a)), "r"(__float_as_uint(b)));
        }
    }

    const int jw = j0 + (lane & 15);
    float wi0 = 0.f, wi1 = 0.f, gn = 1.f, bs = 0.f;
    if (w == 0 && lane < 16) {
        wi0 = Win[jw];
        wi1 = Win[RDIM + jw];
        gn  = gain[jw];
        bs  = bias[jw];
    }

    const int  gbase   = tid * 8;
    const bool gactive = (gbase < RDIM);
    if (!gactive) {
#pragma unroll
        for (int c = 0; c < 8; c++) {
            h_s[0][gbase + c] = 0.f;
            h_s[1][gbase + c] = 0.f;
        }
    }

    for (int t = 0; t < TSTEPS; t++) {
        float* hs = h_s[t & 1];
        float xt = __ldg(&x[t]);

        // ---- Gather h_t: batched polls, bounded spin with global abort ----
        if (gactive) {
            const float2* gp = &g_hbuf[t & 1][gbase];
            unsigned q[4][4];
#pragma unroll
            for (int c = 0; c < 4; c++) {
                asm volatile("ld.global.cg.v4.b32 {%0,%1,%2,%3},[%4];"
                             : "=r"(q[c][0]), "=r"(q[c][1]),
                               "=r"(q[c][2]), "=r"(q[c][3])
                             : "l"(gp + c * 2));
            }
#pragma unroll
            for (int c = 0; c < 4; c++) {
                unsigned tries = 0;
                while (q[c][1] < (unsigned)t || q[c][3] < (unsigned)t) {
                    if ((++tries & 63u) == 0u) {
                        int ab;
                        asm volatile("ld.global.cg.b32 %0,[%1];"
                                     : "=r"(ab) : "l"(&g_abort));
                        if (ab) break;
                        if (tries > SPIN_CAP) {
                            asm volatile("st.global.cg.b32 [%0],%1;"
                                         :: "l"(&g_abort), "r"(1) : "memory");
                            break;
                        }
                    }
                    asm volatile("ld.global.cg.v4.b32 {%0,%1,%2,%3},[%4];"
                                 : "=r"(q[c][0]), "=r"(q[c][1]),
                                   "=r"(q[c][2]), "=r"(q[c][3])
                                 : "l"(gp + c * 2));
                }
            }
            float4 va = make_float4(__uint_as_float(q[0][0]), __uint_as_float(q[0][2]),
                                    __uint_as_float(q[1][0]), __uint_as_float(q[1][2]));
            float4 vb = make_float4(__uint_as_float(q[2][0]), __uint_as_float(q[2][2]),
                                    __uint_as_float(q[3][0]), __uint_as_float(q[3][2]));
            *(float4*)&hs[gbase]     = va;
            *(float4*)&hs[gbase + 4] = vb;
        }
        __syncthreads();   // BAR_A: h_s[t&1] complete

        // ---- Matvec: 8 i's x 16 cols per thread, packed f32x2 ----
        float4 ha = *(const float4*)&hs[ibase];
        float4 hb = *(const float4*)&hs[ibase + 4];
        float hv[8] = {ha.x, ha.y, ha.z, ha.w, hb.x, hb.y, hb.z, hb.w};
        unsigned long long accp[8];
#pragma unroll
        for (int c = 0; c < 8; c++) accp[c] = 0ull;
#pragma unroll
        for (int il = 0; il < 8; il++) {
            unsigned long long hh;
            unsigned hu = __float_as_uint(hv[il]);
            asm("mov.b64 %0,{%1,%1};" : "=l"(hh) : "r"(hu));
#pragma unroll
            for (int c = 0; c < 8; c++)
                asm("fma.rn.f32x2 %0,%1,%2,%3;"
                    : "=l"(accp[c]) : "l"(hh), "l"(wreg[il * 8 + c]), "l"(accp[c]));
        }

        // ---- Reduce-scatter: lanes {2c,2c+1} end with column c's sum ----
        unsigned long long v[4];
        {
            bool hi = (lane & 16) != 0;
#pragma unroll
            for (int k = 0; k < 4; k++) {
                unsigned long long snd = hi ? accp[k] : accp[k + 4];
                unsigned long long rcv = __shfl_xor_sync(0xffffffffu, snd, 16);
                v[k] = addx2(hi ? accp[k + 4] : accp[k], rcv);
            }
        }
        unsigned long long u2[2];
        {
            bool hi = (lane & 8) != 0;
#pragma unroll
            for (int k = 0; k < 2; k++) {
                unsigned long long snd = hi ? v[k] : v[k + 2];
                unsigned long long rcv = __shfl_xor_sync(0xffffffffu, snd, 8);
                u2[k] = addx2(hi ? v[k + 2] : v[k], rcv);
            }
        }
        unsigned long long w64;
        {
            bool hi = (lane & 4) != 0;
            unsigned long long snd = hi ? u2[0] : u2[1];
            unsigned long long rcv = __shfl_xor_sync(0xffffffffu, snd, 4);
            w64 = addx2(hi ? u2[1] : u2[0], rcv);
        }
        float fsum;
        {
            float lo, hi_f;
            asm("mov.b64 {%0,%1},%2;" : "=f"(lo), "=f"(hi_f) : "l"(w64));
            bool hi = (lane & 2) != 0;
            float snd = hi ? lo : hi_f;
            float rcv = __shfl_xor_sync(0xffffffffu, snd, 2);
            fsum = (hi ? hi_f : lo) + rcv;
        }
        fsum += __shfl_xor_sync(0xffffffffu, fsum, 1);

        if ((lane & 1) == 0) part[lane >> 1][w] = fsum;
        __syncthreads();   // BAR_B: part[][] complete

        // ---- Warp 0 finalizes 16 columns, publishes one 128B line ----
        if (w == 0 && lane < 16) {
            float4 pa = *(const float4*)&part[lane][0];
            float4 pb = *(const float4*)&part[lane][4];
            float acc = ((pa.x + pa.y) + (pa.z + pa.w))
                      + ((pb.x + pb.y) + (pb.z + pb.w));
            float pre  = fmaf(xt, wi0, wi1) + acc;
            float hold = hs[jw];
            float hn   = 0.7f * hold + 0.3f * tanhf(fmaf(gn, pre, bs));
            out[(size_t)t * RDIM + jw] = hn;
            unsigned long long pkt;
            asm("mov.b64 %0,{%1,%2};" : "=l"(pkt)
                : "r"(__float_as_uint(hn)), "r"((unsigned)(t + 1)));
            asm volatile("st.global.cg.u64 [%0],%1;"
                         :: "l"(&g_hbuf[(t + 1) & 1][jw]), "l"(pkt) : "memory");
        }
        // No trailing barrier (see R4 ordering argument).
    }
}

// ======================== STEPPED (fallback) PATH ===========================
// One launch per timestep; kernel boundary is the global barrier. W streams
// from L2 (16 MB, L2-resident). Cannot deadlock regardless of residency.
__global__ void __launch_bounds__(NTHR) esn_step_kernel(
    const float* __restrict__ x, const float* __restrict__ Win,
    const float* __restrict__ W, const float* __restrict__ gain,
    const float* __restrict__ bias, float* __restrict__ out, int t)
{
    __shared__ float red[16][16];
    const int tid = threadIdx.x;
    const int c = tid & 15;        // column within CTA
    const int g = tid >> 4;        // i-group
    const int j = blockIdx.x * COLS + c;
    const float* hp = g_hs[t & 1];

    float acc = 0.f;
#pragma unroll 5
    for (int i = g; i < RDIM; i += 16)
        acc = fmaf(hp[i], W[(size_t)i * RDIM + j], acc);
    red[g][c] = acc;
    __syncthreads();

    if (tid < 16) {
        int jc = blockIdx.x * COLS + tid;
        float s = 0.f;
#pragma unroll
        for (int k = 0; k < 16; k++) s += red[k][tid];
        float xt   = __ldg(&x[t]);
        float pre  = fmaf(xt, Win[jc], Win[RDIM + jc]) + s;
        float hold = hp[jc];
        float hn   = 0.7f * hold + 0.3f * tanhf(fmaf(gain[jc], pre, bias[jc]));
        out[(size_t)t * RDIM + jc] = hn;
        g_hs[(t + 1) & 1][jc] = hn;
    }
}

extern "C" void kernel_launch(void* const* d_in, const int* in_sizes, int n_in,
                              void* d_out, int out_size) {
    const float* x    = (const float*)d_in[0];
    const float* Win  = (const float*)d_in[1];
    const float* W    = (const float*)d_in[2];
    const float* gain = (const float*)d_in[3];
    const float* bias = (const float*)d_in[4];
    float* out = (float*)d_out;
    (void)in_sizes; (void)n_in; (void)out_size;

    // Residency gate (pure queries: capture-safe, deterministic).
    int dev = 0, sms = 0, maxb = 0;
    cudaGetDevice(&dev);
    cudaDeviceGetAttribute(&sms, cudaDevAttrMultiProcessorCount, dev);
    cudaOccupancyMaxActiveBlocksPerMultiprocessor(&maxb, esn_kernel, NTHR, 0);
    bool fused_ok = (maxb >= 1) && ((long long)sms * maxb >= NCTA) && (sms >= NCTA);

    esn_init_kernel<<<16, 256>>>();
    if (fused_ok) {
        esn_kernel<<<NCTA, NTHR>>>(x, Win, W, gain, bias, out);
    } else {
        for (int t = 0; t < TSTEPS; t++)
            esn_step_kernel<<<NCTA, NTHR>>>(x, Win, W, gain, bias, out, t);
    }
}

// round 7
// speedup vs baseline: 1.4496x; 1.4496x over previous
#include <cuda_runtime.h>
#include <cstdint>
#include <cmath>

#define RDIM 2000
#define TSTEPS 20000
#define NCTA 125
#define COLS 16          // columns per CTA (125*16 = 2000)
#define NTHR 256
#define RPAD 2048
#define SPIN_CAP (1u << 20)

// Plain state values, double-buffered by step parity. buf[t&1] holds h_t.
__device__ float g_hval[2][RPAD];
// Epoch counter: total number of per-CTA publishes. h_t readable when >= 125*t.
__device__ unsigned g_cnt;
// Watchdog: set when a spin exceeds SPIN_CAP; all spinners then bail.
__device__ int g_abort;
// State buffers for the stepped fallback path.
__device__ float g_hs[2][RPAD];

__global__ void esn_init_kernel() {
    int idx = blockIdx.x * blockDim.x + threadIdx.x;   // 16*256 = 4096
    if (idx < 2 * RPAD) {
        ((float*)g_hval)[idx] = 0.f;
        ((float*)g_hs)[idx]   = 0.f;
    }
    if (idx == 0) { g_cnt = 0u; g_abort = 0; }
}

__device__ __forceinline__ unsigned long long addx2(unsigned long long a,
                                                    unsigned long long b) {
    unsigned long long r;
    asm("add.rn.f32x2 %0,%1,%2;" : "=l"(r) : "l"(a), "l"(b));
    return r;
}

// ============================ FUSED (fast) PATH =============================
__global__ void __launch_bounds__(NTHR, 1) esn_kernel(
    const float* __restrict__ x,     // [T,1]
    const float* __restrict__ Win,   // [2,R]
    const float* __restrict__ W,     // [R,R] row-major
    const float* __restrict__ gain,  // [R]
    const float* __restrict__ bias,  // [R]
    float* __restrict__ out)         // [T,R]
{
    __shared__ __align__(16) float part[COLS][8];   // per-warp column partials

    const int tid  = threadIdx.x;
    const int lane = tid & 31;
    const int w    = tid >> 5;
    const int j0   = blockIdx.x * COLS;    // CTA's 16 columns
    const int ibase = tid * 8;             // 8 consecutive i's (== gather slice)

    // W slice: wreg[il*8+c] packs (W[i][j0+2c], W[i][j0+2c+1]), i = ibase+il.
    unsigned long long wreg[64];
#pragma unroll
    for (int il = 0; il < 8; il++) {
        int i = ibase + il;
#pragma unroll
        for (int c = 0; c < 8; c++) {
            float a = (i < RDIM) ? W[(size_t)i * RDIM + j0 + 2 * c]     : 0.f;
            float b = (i < RDIM) ? W[(size_t)i * RDIM + j0 + 2 * c + 1] : 0.f;
            asm("mov.b64 %0,{%1,%2};" : "=l"(wreg[il * 8 + c])
                : "r"(__float_as_uint(a)), "r"(__float_as_uint(b)));
        }
    }

    // Publisher constants (warp 0, lanes 0..15 own columns j0..j0+15).
    const int jw = j0 + (lane & 15);
    float wi0 = 0.f, wi1 = 0.f, gn = 1.f, bs = 0.f, h_prev = 0.f;
    if (w == 0 && lane < 16) {
        wi0 = Win[jw];
        wi1 = Win[RDIM + jw];
        gn  = gain[jw];
        bs  = bias[jw];
    }

    unsigned target = 0;       // counter threshold for step t: 125*t
    bool dead = false;         // sticky after watchdog abort (tid 0 only)
    unsigned* const cp = &g_cnt;

    for (int t = 0; t < TSTEPS; t++) {
        float xt = __ldg(&x[t]);

        // ---- Single-thread acquire-poll on the epoch counter ----
        if (tid == 0 && target != 0u && !dead) {
            unsigned cv, tries = 0;
            for (;;) {
                asm volatile("ld.acquire.gpu.global.b32 %0,[%1];"
                             : "=r"(cv) : "l"(cp));
                if (cv >= target) break;
                if ((++tries & 255u) == 0u) {
                    int ab;
                    asm volatile("ld.global.cg.b32 %0,[%1];"
                                 : "=r"(ab) : "l"(&g_abort));
                    if (ab) { dead = true; break; }
                    if (tries > SPIN_CAP) {
                        asm volatile("st.global.cg.b32 [%0],%1;"
                                     :: "l"(&g_abort), "r"(1) : "memory");
                        dead = true; break;
                    }
                }
            }
        }
        __syncthreads();   // BAR1: broadcasts tid0's acquire to the whole CTA

        // ---- Gather this thread's 8 h values straight into registers ----
        float h0, h1, h2, h3, h4, h5, h6, h7;
        {
            const float* gp = &g_hval[t & 1][ibase];
            asm volatile("ld.global.cg.v4.f32 {%0,%1,%2,%3},[%4];"
                         : "=f"(h0), "=f"(h1), "=f"(h2), "=f"(h3) : "l"(gp));
            asm volatile("ld.global.cg.v4.f32 {%0,%1,%2,%3},[%4];"
                         : "=f"(h4), "=f"(h5), "=f"(h6), "=f"(h7) : "l"(gp + 4));
        }
        float hv[8] = {h0, h1, h2, h3, h4, h5, h6, h7};

        // ---- Matvec: 8 i's x 16 cols per thread, packed f32x2 ----
        unsigned long long accp[8];
#pragma unroll
        for (int c = 0; c < 8; c++) accp[c] = 0ull;
#pragma unroll
        for (int il = 0; il < 8; il++) {
            unsigned long long hh;
            unsigned hu = __float_as_uint(hv[il]);
            asm("mov.b64 %0,{%1,%1};" : "=l"(hh) : "r"(hu));
#pragma unroll
            for (int c = 0; c < 8; c++)
                asm("fma.rn.f32x2 %0,%1,%2,%3;"
                    : "=l"(accp[c]) : "l"(hh), "l"(wreg[il * 8 + c]), "l"(accp[c]));
        }

        // ---- Reduce-scatter: lanes {2c,2c+1} end with column c's warp sum ----
        unsigned long long v[4];
        {
            bool hi = (lane & 16) != 0;
#pragma unroll
            for (int k = 0; k < 4; k++) {
                unsigned long long snd = hi ? accp[k] : accp[k + 4];
                unsigned long long rcv = __shfl_xor_sync(0xffffffffu, snd, 16);
                v[k] = addx2(hi ? accp[k + 4] : accp[k], rcv);
            }
        }
        unsigned long long u2[2];
        {
            bool hi = (lane & 8) != 0;
#pragma unroll
            for (int k = 0; k < 2; k++) {
                unsigned long long snd = hi ? v[k] : v[k + 2];
                unsigned long long rcv = __shfl_xor_sync(0xffffffffu, snd, 8);
                u2[k] = addx2(hi ? v[k + 2] : v[k], rcv);
            }
        }
        unsigned long long w64;
        {
            bool hi = (lane & 4) != 0;
            unsigned long long snd = hi ? u2[0] : u2[1];
            unsigned long long rcv = __shfl_xor_sync(0xffffffffu, snd, 4);
            w64 = addx2(hi ? u2[1] : u2[0], rcv);
        }
        float fsum;
        {
            float lo, hi_f;
            asm("mov.b64 {%0,%1},%2;" : "=f"(lo), "=f"(hi_f) : "l"(w64));
            bool hi = (lane & 2) != 0;
            float snd = hi ? lo : hi_f;
            float rcv = __shfl_xor_sync(0xffffffffu, snd, 2);
            fsum = (hi ? hi_f : lo) + rcv;
        }
        fsum += __shfl_xor_sync(0xffffffffu, fsum, 1);

        if ((lane & 1) == 0) part[lane >> 1][w] = fsum;
        __syncthreads();   // BAR2: part complete AND all gathers of step t done

        // ---- Warp 0 finalizes 16 columns; publish + release-increment ----
        if (w == 0) {
            if (lane < 16) {
                float4 pa = *(const float4*)&part[lane][0];
                float4 pb = *(const float4*)&part[lane][4];
                float acc = ((pa.x + pa.y) + (pa.z + pa.w))
                          + ((pb.x + pb.y) + (pb.z + pb.w));
                float pre = fmaf(xt, wi0, wi1) + acc;   // u_t[j] + (hW)[j]
                float hn  = 0.7f * h_prev + 0.3f * tanhf(fmaf(gn, pre, bs));
                out[(size_t)t * RDIM + jw] = hn;
                asm volatile("st.global.cg.b32 [%0],%1;"
                             :: "l"(&g_hval[(t + 1) & 1][jw]),
                                "r"(__float_as_uint(hn)) : "memory");
                h_prev = hn;
            }
            __syncwarp(0xffffffffu);
            if (lane == 0) {
                // Release-atomic: orders the 16 h-value stores before the
                // increment, without a separate full fence.
                asm volatile("red.release.gpu.global.add.u32 [%0],%1;"
                             :: "l"(cp), "r"(1u) : "memory");
            }
        }
        target += 125u;
        // No trailing barrier: next step's poll (tid 0) gates everything, and
        // part[][] is rewritten only after the next BAR1.
    }
}

// ======================== STEPPED (fallback) PATH ===========================
__global__ void __launch_bounds__(NTHR) esn_step_kernel(
    const float* __restrict__ x, const float* __restrict__ Win,
    const float* __restrict__ W, const float* __restrict__ gain,
    const float* __restrict__ bias, float* __restrict__ out, int t)
{
    __shared__ float red[16][16];
    const int tid = threadIdx.x;
    const int c = tid & 15;
    const int g = tid >> 4;
    const int j = blockIdx.x * COLS + c;
    const float* hp = g_hs[t & 1];

    float acc = 0.f;
#pragma unroll 5
    for (int i = g; i < RDIM; i += 16)
        acc = fmaf(hp[i], W[(size_t)i * RDIM + j], acc);
    red[g][c] = acc;
    __syncthreads();

    if (tid < 16) {
        int jc = blockIdx.x * COLS + tid;
        float s = 0.f;
#pragma unroll
        for (int k = 0; k < 16; k++) s += red[k][tid];
        float xt   = __ldg(&x[t]);
        float pre  = fmaf(xt, Win[jc], Win[RDIM + jc]) + s;
        float hold = hp[jc];
        float hn   = 0.7f * hold + 0.3f * tanhf(fmaf(gain[jc], pre, bias[jc]));
        out[(size_t)t * RDIM + jc] = hn;
        g_hs[(t + 1) & 1][jc] = hn;
    }
}

extern "C" void kernel_launch(void* const* d_in, const int* in_sizes, int n_in,
                              void* d_out, int out_size) {
    const float* x    = (const float*)d_in[0];
    const float* Win  = (const float*)d_in[1];
    const float* W    = (const float*)d_in[2];
    const float* gain = (const float*)d_in[3];
    const float* bias = (const float*)d_in[4];
    float* out = (float*)d_out;
    (void)in_sizes; (void)n_in; (void)out_size;

    int dev = 0, sms = 0, maxb = 0;
    cudaGetDevice(&dev);
    cudaDeviceGetAttribute(&sms, cudaDevAttrMultiProcessorCount, dev);
    cudaOccupancyMaxActiveBlocksPerMultiprocessor(&maxb, esn_kernel, NTHR, 0);
    bool fused_ok = (maxb >= 1) && ((long long)sms * maxb >= NCTA) && (sms >= NCTA);

    esn_init_kernel<<<16, 256>>>();
    if (fused_ok) {
        esn_kernel<<<NCTA, NTHR>>>(x, Win, W, gain, bias, out);
    } else {
        for (int t = 0; t < TSTEPS; t++)
            esn_step_kernel<<<NCTA, NTHR>>>(x, Win, W, gain, bias, out, t);
    }
}